// round 3
// baseline (speedup 1.0000x reference)
#include <cuda_runtime.h>
#include <math.h>

// Problem constants
#define RR 128
#define CC 256
#define EE 768
#define HH 12
#define DD 64
#define MTOK (RR * CC)   // 32768 tokens

// q scaling: (D^-0.5) / sqrt(R) = 0.125 / sqrt(128)
#define QSCALE (0.0110485434560398f)

// Scratch (device globals — allocation-free per harness rules)
__device__ float g_q[(size_t)MTOK * EE];
__device__ float g_k[(size_t)MTOK * EE];
__device__ float g_v[(size_t)MTOK * EE];
__device__ float g_ctx[(size_t)MTOK * EE];
__device__ float g_attn[(size_t)HH * CC * CC];

// ---------------------------------------------------------------------------
// Classic 128x128x8 SGEMM tile, 256 threads, 8x8 per-thread microtile.
// A: [M,K] row-major, B: [K,N] row-major, C: [M,N] row-major.
// C = (A@B + bias) * scale  on the (bm,bn) 128x128 tile.
// Requires K % 8 == 0, N % 4 == 0, tile fully in-bounds.
// ---------------------------------------------------------------------------
__device__ __forceinline__ void gemm128x128(
    const float* __restrict__ A, const float* __restrict__ B,
    const float* __restrict__ bias, float* __restrict__ C,
    int bm, int bn, int N, int K, float scale)
{
    __shared__ float As[8][128];   // transposed: As[k][m]
    __shared__ float Bs[8][128];   // Bs[k][n]

    const int tid = threadIdx.x;          // 0..255
    const int tx = tid & 15;              // 16 thread-cols
    const int ty = tid >> 4;              // 16 thread-rows

    const float* Ablk = A + (size_t)bm * 128 * K;
    const float* Bblk = B + (size_t)bn * 128;

    // A-tile load: 128 rows x 8 k  -> each thread one float4 along k
    const int arow = tid >> 1;            // 0..127
    const int acol = (tid & 1) * 4;       // 0 or 4
    // B-tile load: 8 k-rows x 128 n -> each thread one float4 along n
    const int brow = tid >> 5;            // 0..7
    const int bcol = (tid & 31) * 4;      // 0..124

    float acc[8][8];
#pragma unroll
    for (int i = 0; i < 8; i++)
#pragma unroll
        for (int j = 0; j < 8; j++) acc[i][j] = 0.0f;

    for (int k0 = 0; k0 < K; k0 += 8) {
        float4 av = *(const float4*)(Ablk + (size_t)arow * K + k0 + acol);
        float4 bv = *(const float4*)(Bblk + (size_t)(k0 + brow) * N + bcol);
        As[acol + 0][arow] = av.x;
        As[acol + 1][arow] = av.y;
        As[acol + 2][arow] = av.z;
        As[acol + 3][arow] = av.w;
        *(float4*)(&Bs[brow][bcol]) = bv;
        __syncthreads();

#pragma unroll
        for (int k = 0; k < 8; k++) {
            float a[8], b[8];
            float4 a0 = *(const float4*)(&As[k][ty * 8]);
            float4 a1 = *(const float4*)(&As[k][ty * 8 + 4]);
            float4 b0 = *(const float4*)(&Bs[k][tx * 8]);
            float4 b1 = *(const float4*)(&Bs[k][tx * 8 + 4]);
            a[0]=a0.x; a[1]=a0.y; a[2]=a0.z; a[3]=a0.w;
            a[4]=a1.x; a[5]=a1.y; a[6]=a1.z; a[7]=a1.w;
            b[0]=b0.x; b[1]=b0.y; b[2]=b0.z; b[3]=b0.w;
            b[4]=b1.x; b[5]=b1.y; b[6]=b1.z; b[7]=b1.w;
#pragma unroll
            for (int i = 0; i < 8; i++)
#pragma unroll
                for (int j = 0; j < 8; j++)
                    acc[i][j] = fmaf(a[i], b[j], acc[i][j]);
        }
        __syncthreads();
    }

    const int crow0 = bm * 128 + ty * 8;
    const int ccol0 = bn * 128 + tx * 8;
    float bb[8];
#pragma unroll
    for (int j = 0; j < 8; j++) bb[j] = bias[ccol0 + j];

#pragma unroll
    for (int i = 0; i < 8; i++) {
        float4 v0, v1;
        v0.x = (acc[i][0] + bb[0]) * scale;
        v0.y = (acc[i][1] + bb[1]) * scale;
        v0.z = (acc[i][2] + bb[2]) * scale;
        v0.w = (acc[i][3] + bb[3]) * scale;
        v1.x = (acc[i][4] + bb[4]) * scale;
        v1.y = (acc[i][5] + bb[5]) * scale;
        v1.z = (acc[i][6] + bb[6]) * scale;
        v1.w = (acc[i][7] + bb[7]) * scale;
        float* crow = C + (size_t)(crow0 + i) * N + ccol0;
        *(float4*)(crow)     = v0;
        *(float4*)(crow + 4) = v1;
    }
}

// ---------------------------------------------------------------------------
// Stage 1: QKV projections. grid = (N/128=6, M/128=256, 3)
// ---------------------------------------------------------------------------
__global__ __launch_bounds__(256) void qkv_kernel(
    const float* __restrict__ x,
    const float* __restrict__ wq, const float* __restrict__ bq,
    const float* __restrict__ wk, const float* __restrict__ bk,
    const float* __restrict__ wv, const float* __restrict__ bv)
{
    const int which = blockIdx.z;
    const float* W    = (which == 0) ? wq : (which == 1) ? wk : wv;
    const float* bias = (which == 0) ? bq : (which == 1) ? bk : bv;
    float* out        = (which == 0) ? g_q : (which == 1) ? g_k : g_v;
    const float scale = (which == 0) ? QSCALE : 1.0f;
    gemm128x128(x, W, bias, out, blockIdx.y, blockIdx.x, EE, EE, scale);
}

// ---------------------------------------------------------------------------
// Stage 5: output projection. grid = (6, 256)
// ---------------------------------------------------------------------------
__global__ __launch_bounds__(256) void out_gemm_kernel(
    const float* __restrict__ wo, const float* __restrict__ bo,
    float* __restrict__ out)
{
    gemm128x128(g_ctx, wo, bo, out, blockIdx.y, blockIdx.x, EE, EE, 1.0f);
}

// ---------------------------------------------------------------------------
// Stage 2: tied-row logits.
// logits[h,i,j] = sum_{r,d} q[r,i,h,d] * k[r,j,h,d]
// grid = (jtiles=4, itiles=4, heads=12), block 256, 64x64 tile, BK=16.
// ---------------------------------------------------------------------------
__global__ __launch_bounds__(256) void logits_kernel()
{
    const int h  = blockIdx.z;
    const int i0 = blockIdx.y * 64;
    const int j0 = blockIdx.x * 64;

    __shared__ float Qs[16][64];   // [d][i]
    __shared__ float Ks[16][64];   // [d][j]

    const int tid = threadIdx.x;
    const int tx = tid & 15;
    const int ty = tid >> 4;
    const int lrow = tid >> 2;        // 0..63
    const int lcol = (tid & 3) * 4;   // 0,4,8,12

    float acc[4][4];
#pragma unroll
    for (int i = 0; i < 4; i++)
#pragma unroll
        for (int j = 0; j < 4; j++) acc[i][j] = 0.0f;

    for (int r = 0; r < RR; r++) {
        const float* qb = g_q + (size_t)(r * CC) * EE + h * DD;
        const float* kb = g_k + (size_t)(r * CC) * EE + h * DD;
#pragma unroll
        for (int d0 = 0; d0 < DD; d0 += 16) {
            float4 qv = *(const float4*)(qb + (size_t)(i0 + lrow) * EE + d0 + lcol);
            float4 kv = *(const float4*)(kb + (size_t)(j0 + lrow) * EE + d0 + lcol);
            Qs[lcol + 0][lrow] = qv.x;
            Qs[lcol + 1][lrow] = qv.y;
            Qs[lcol + 2][lrow] = qv.z;
            Qs[lcol + 3][lrow] = qv.w;
            Ks[lcol + 0][lrow] = kv.x;
            Ks[lcol + 1][lrow] = kv.y;
            Ks[lcol + 2][lrow] = kv.z;
            Ks[lcol + 3][lrow] = kv.w;
            __syncthreads();
#pragma unroll
            for (int k = 0; k < 16; k++) {
                float a[4], b[4];
                float4 av = *(const float4*)(&Qs[k][ty * 4]);
                float4 bv = *(const float4*)(&Ks[k][tx * 4]);
                a[0]=av.x; a[1]=av.y; a[2]=av.z; a[3]=av.w;
                b[0]=bv.x; b[1]=bv.y; b[2]=bv.z; b[3]=bv.w;
#pragma unroll
                for (int i = 0; i < 4; i++)
#pragma unroll
                    for (int j = 0; j < 4; j++)
                        acc[i][j] = fmaf(a[i], b[j], acc[i][j]);
            }
            __syncthreads();
        }
    }

    float* L = g_attn + (size_t)h * CC * CC;
#pragma unroll
    for (int i = 0; i < 4; i++) {
        float4 v;
        v.x = acc[i][0]; v.y = acc[i][1]; v.z = acc[i][2]; v.w = acc[i][3];
        *(float4*)(L + (size_t)(i0 + ty * 4 + i) * CC + j0 + tx * 4) = v;
    }
}

// ---------------------------------------------------------------------------
// Stage 3: softmax over last axis (rows of length 256), in place on g_attn.
// grid = H*C = 3072 blocks, 256 threads.
// ---------------------------------------------------------------------------
__global__ __launch_bounds__(256) void softmax_kernel()
{
    float* p = g_attn + (size_t)blockIdx.x * CC;
    const int t = threadIdx.x;
    __shared__ float red[256];

    float v = p[t];
    red[t] = v;
    __syncthreads();
#pragma unroll
    for (int s = 128; s > 0; s >>= 1) {
        if (t < s) red[t] = fmaxf(red[t], red[t + s]);
        __syncthreads();
    }
    const float m = red[0];
    __syncthreads();

    const float e = __expf(v - m);
    red[t] = e;
    __syncthreads();
#pragma unroll
    for (int s = 128; s > 0; s >>= 1) {
        if (t < s) red[t] += red[t + s];
        __syncthreads();
    }
    p[t] = e / red[0];
}

// ---------------------------------------------------------------------------
// Stage 4: context[r,i,h,d] = sum_j probs[h,i,j] * v[r,j,h,d]
// grid = (itiles=4, r=128, h=12), block 256, 64(i) x 64(d) tile, BK=16(j).
// ---------------------------------------------------------------------------
__global__ __launch_bounds__(256) void context_kernel()
{
    const int h  = blockIdx.z;
    const int r  = blockIdx.y;
    const int i0 = blockIdx.x * 64;

    __shared__ float Ps[16][64];   // [j][i]
    __shared__ float Vs[16][64];   // [j][d]

    const int tid = threadIdx.x;
    const int tx = tid & 15;
    const int ty = tid >> 4;
    const int prow = tid >> 2;         // i: 0..63
    const int pcol = (tid & 3) * 4;    // j4
    const int vrow = tid >> 4;         // j: 0..15
    const int vcol = (tid & 15) * 4;   // d

    float acc[4][4];
#pragma unroll
    for (int i = 0; i < 4; i++)
#pragma unroll
        for (int j = 0; j < 4; j++) acc[i][j] = 0.0f;

    const float* P = g_attn + (size_t)h * CC * CC;
    const float* V = g_v + (size_t)(r * CC) * EE + h * DD;

    for (int j0 = 0; j0 < CC; j0 += 16) {
        float4 pv = *(const float4*)(P + (size_t)(i0 + prow) * CC + j0 + pcol);
        Ps[pcol + 0][prow] = pv.x;
        Ps[pcol + 1][prow] = pv.y;
        Ps[pcol + 2][prow] = pv.z;
        Ps[pcol + 3][prow] = pv.w;
        float4 vv = *(const float4*)(V + (size_t)(j0 + vrow) * EE + vcol);
        *(float4*)(&Vs[vrow][vcol]) = vv;
        __syncthreads();
#pragma unroll
        for (int k = 0; k < 16; k++) {
            float a[4], b[4];
            float4 av = *(const float4*)(&Ps[k][ty * 4]);
            float4 bv = *(const float4*)(&Vs[k][tx * 4]);
            a[0]=av.x; a[1]=av.y; a[2]=av.z; a[3]=av.w;
            b[0]=bv.x; b[1]=bv.y; b[2]=bv.z; b[3]=bv.w;
#pragma unroll
            for (int i = 0; i < 4; i++)
#pragma unroll
                for (int j = 0; j < 4; j++)
                    acc[i][j] = fmaf(a[i], b[j], acc[i][j]);
        }
        __syncthreads();
    }

    // write ctx[(r*CC + i0 + ty*4 + i)*EE + h*DD + tx*4 + j]
#pragma unroll
    for (int i = 0; i < 4; i++) {
        float4 v;
        v.x = acc[i][0]; v.y = acc[i][1]; v.z = acc[i][2]; v.w = acc[i][3];
        *(float4*)(g_ctx + (size_t)(r * CC + i0 + ty * 4 + i) * EE + h * DD + tx * 4) = v;
    }
}

// ---------------------------------------------------------------------------
extern "C" void kernel_launch(void* const* d_in, const int* in_sizes, int n_in,
                              void* d_out, int out_size)
{
    (void)in_sizes; (void)n_in; (void)out_size;
    const float* x  = (const float*)d_in[0];
    const float* wq = (const float*)d_in[1];
    const float* bq = (const float*)d_in[2];
    const float* wk = (const float*)d_in[3];
    const float* bk = (const float*)d_in[4];
    const float* wv = (const float*)d_in[5];
    const float* bv = (const float*)d_in[6];
    const float* wo = (const float*)d_in[7];
    const float* bo = (const float*)d_in[8];
    float* out = (float*)d_out;

    dim3 g1(EE / 128, MTOK / 128, 3);          // (6, 256, 3)
    qkv_kernel<<<g1, 256>>>(x, wq, bq, wk, bk, wv, bv);

    dim3 g2(CC / 64, CC / 64, HH);             // (4, 4, 12)
    logits_kernel<<<g2, 256>>>();

    softmax_kernel<<<HH * CC, 256>>>();        // 3072 blocks

    dim3 g4(CC / 64, RR, HH);                  // (4, 128, 12)
    context_kernel<<<g4, 256>>>();

    dim3 g5(EE / 128, MTOK / 128);             // (6, 256)
    out_gemm_kernel<<<g5, 256>>>(wo, bo, out);
}

// round 7
// speedup vs baseline: 1.9083x; 1.9083x over previous
#include <cuda_runtime.h>
#include <cuda_bf16.h>
#include <stdint.h>
#include <math.h>

// ---------------------------------------------------------------------------
// Problem constants
// ---------------------------------------------------------------------------
#define RR 128
#define CC 256
#define EE 768
#define HH 12
#define DD 64
#define MTOK (RR * CC)            // 32768 tokens
#define QSCALE (0.0110485434560398f)   // (1/8) / sqrt(128)

// ---------------------------------------------------------------------------
// mma.sync GEMM tiling (stages 1 & 5): CTA 128x128, BK=32, 8 warps (4M x 2N)
// ---------------------------------------------------------------------------
#define BM 128
#define BN 128
#define BK 32
#define NKB (EE / BK)             // 24
#define KPAD 40                   // bf16 elems per smem row (32 + 8 pad) = 80 B
#define ROWB (KPAD * 2)           // 80 bytes per row
#define TILE_B (BM * ROWB)        // 10240 bytes per (hi or lo) tile
#define AHI 0
#define ALO TILE_B
#define BHI (2 * TILE_B)
#define BLO (3 * TILE_B)
#define BUF_B (4 * TILE_B)        // 40960 bytes per k-block buffer
#define SMEM_TOTAL (2 * BUF_B)    // 81920 bytes

// ---------------------------------------------------------------------------
// Device global scratch (allocation-free per harness rules)
// ---------------------------------------------------------------------------
__device__ float    g_q[(size_t)MTOK * EE];
__device__ float    g_k[(size_t)MTOK * EE];
__device__ float    g_v[(size_t)MTOK * EE];
__device__ float    g_attn[(size_t)HH * CC * CC];
__device__ uint32_t g_xp[(size_t)MTOK * EE];     // x packed (hi bf16 | lo bf16<<16)
__device__ uint32_t g_ctxp[(size_t)MTOK * EE];   // context packed
__device__ uint32_t g_wt[4 * (size_t)EE * EE];   // transposed packed weights [n][k]

// ---------------------------------------------------------------------------
// Helpers
// ---------------------------------------------------------------------------
__device__ __forceinline__ uint32_t smem_to_u32(const void* p) {
    uint32_t a;
    asm("{ .reg .u64 t; cvta.to.shared.u64 t, %1; cvt.u32.u64 %0, t; }"
        : "=r"(a) : "l"(p));
    return a;
}

#define STS64(addr, val) \
    asm volatile("st.shared.b64 [%0], %1;" :: "r"(addr), "l"(val) : "memory")

#define LDSM4(r, addr) \
    asm volatile("ldmatrix.sync.aligned.m8n8.x4.shared.b16 {%0,%1,%2,%3}, [%4];" \
        : "=r"((r)[0]), "=r"((r)[1]), "=r"((r)[2]), "=r"((r)[3]) : "r"(addr))

__device__ __forceinline__ void mma_bf16(float* c, const uint32_t* a,
                                         uint32_t b0, uint32_t b1) {
    asm volatile(
        "mma.sync.aligned.m16n8k16.row.col.f32.bf16.bf16.f32 "
        "{%0,%1,%2,%3}, {%4,%5,%6,%7}, {%8,%9}, {%0,%1,%2,%3};"
        : "+f"(c[0]), "+f"(c[1]), "+f"(c[2]), "+f"(c[3])
        : "r"(a[0]), "r"(a[1]), "r"(a[2]), "r"(a[3]), "r"(b0), "r"(b1));
}

// split-bf16 packing: low 16 bits = hi bf16, high 16 bits = lo bf16
__device__ __forceinline__ uint32_t pack_bf16_split(float f) {
    __nv_bfloat16 h = __float2bfloat16(f);
    float r = f - __bfloat162float(h);
    __nv_bfloat16 l = __float2bfloat16(r);
    return (uint32_t)__bfloat16_as_ushort(h) | ((uint32_t)__bfloat16_as_ushort(l) << 16);
}

// extract (hi,hi) / (lo,lo) bf16 pairs from two packed elems
__device__ __forceinline__ uint64_t hi_quad(uint4 v) {
    uint32_t h01 = __byte_perm(v.x, v.y, 0x5410);
    uint32_t h23 = __byte_perm(v.z, v.w, 0x5410);
    return (uint64_t)h01 | ((uint64_t)h23 << 32);
}
__device__ __forceinline__ uint64_t lo_quad(uint4 v) {
    uint32_t l01 = __byte_perm(v.x, v.y, 0x7632);
    uint32_t l23 = __byte_perm(v.z, v.w, 0x7632);
    return (uint64_t)l01 | ((uint64_t)l23 << 32);
}

// ---------------------------------------------------------------------------
// Pack kernels
// ---------------------------------------------------------------------------
__global__ __launch_bounds__(256) void pack_x_kernel(const float* __restrict__ x)
{
    size_t idx = (size_t)blockIdx.x * 256 + threadIdx.x;   // float4 index
    float4 v = ((const float4*)x)[idx];
    uint4 o;
    o.x = pack_bf16_split(v.x);
    o.y = pack_bf16_split(v.y);
    o.z = pack_bf16_split(v.z);
    o.w = pack_bf16_split(v.w);
    ((uint4*)g_xp)[idx] = o;
}

// Transposed packed weights: g_wt[mat][n*EE + k] = split(W[k*EE + n])
// SMEM-tiled 32x32 transpose: coalesced reads and writes.
__global__ __launch_bounds__(256) void pack_wt_kernel(
    const float* __restrict__ wq, const float* __restrict__ wk,
    const float* __restrict__ wv, const float* __restrict__ wo)
{
    const int mat = blockIdx.z;
    const float* W = (mat == 0) ? wq : (mat == 1) ? wk : (mat == 2) ? wv : wo;
    __shared__ float s[32][33];
    const int k0 = blockIdx.y * 32, n0 = blockIdx.x * 32;
    const int tx = threadIdx.x & 31, ty = threadIdx.x >> 5;   // 32 x 8
#pragma unroll
    for (int i = 0; i < 32; i += 8)
        s[ty + i][tx] = W[(size_t)(k0 + ty + i) * EE + n0 + tx];
    __syncthreads();
    uint32_t* dst = g_wt + (size_t)mat * EE * EE;
#pragma unroll
    for (int i = 0; i < 32; i += 8)
        dst[(size_t)(n0 + ty + i) * EE + k0 + tx] = pack_bf16_split(s[tx][ty + i]);
}

// ---------------------------------------------------------------------------
// Split-bf16 mma.sync GEMM core.
//   A packed [M x 768] row-major, Bt packed [768(n) x 768(k)] row-major.
//   C (fp32) = (A @ Bt^T + bias) * scale on tile (m0, n0) of size 128x128.
// ---------------------------------------------------------------------------
__device__ void gemm_mma_body(
    const uint4* __restrict__ Apk, const uint4* __restrict__ Bpk,
    const float* __restrict__ bias, float* __restrict__ C,
    float scale, int m0, int n0)
{
    extern __shared__ char smem[];
    const uint32_t sb = smem_to_u32(smem);
    const int tid  = threadIdx.x;
    const int lane = tid & 31;
    const int w    = tid >> 5;
    const int wy   = w & 3;        // M warp (0..3) -> m offset wy*32
    const int wx   = w >> 2;       // N warp (0..1) -> n offset wx*64

    // ---- global load coordinates: thread covers rows lrow+{0,32,64,96} ----
    const int lrow = tid >> 3;     // 0..31
    const int lkq  = tid & 7;      // uint4 col within 32-elem k-block

    // ---- ldmatrix per-lane byte offsets (within a hi/lo tile) ----
    // A x4: row = m + (lane&15), kcol = (lane>>4)*8
    const uint32_t aoff0 = (uint32_t)((wy * 32 + (lane & 15)) * ROWB + ((lane >> 4) * 8) * 2);
    const uint32_t aoff1 = aoff0 + 16 * ROWB;
    // B x4: row = n + ((lane>>4)&1)*8 + (lane&7), kcol = ((lane>>3)&1)*8
    const uint32_t brow  = (uint32_t)(wx * 64 + ((lane >> 4) & 1) * 8 + (lane & 7));
    const uint32_t bkc   = (uint32_t)(((lane >> 3) & 1) * 8) * 2;
    uint32_t boff[4];
#pragma unroll
    for (int np = 0; np < 4; np++)
        boff[np] = (brow + np * 16) * ROWB + bkc;

    float acc[2][8][4];
#pragma unroll
    for (int mi = 0; mi < 2; mi++)
#pragma unroll
        for (int nf = 0; nf < 8; nf++)
#pragma unroll
            for (int r = 0; r < 4; r++) acc[mi][nf][r] = 0.0f;

    uint4 pa[4], pb[4];
    // prefetch k-block 0
#pragma unroll
    for (int it = 0; it < 4; it++) {
        pa[it] = Apk[(size_t)(m0 + lrow + it * 32) * (EE / 4) + lkq];
        pb[it] = Bpk[(size_t)(n0 + lrow + it * 32) * (EE / 4) + lkq];
    }
    {
        const uint32_t base = sb;  // buffer 0
        const uint32_t so = (uint32_t)(lrow * ROWB + lkq * 8);
#pragma unroll
        for (int it = 0; it < 4; it++) {
            uint32_t ro = so + it * 32 * ROWB;
            STS64(base + AHI + ro, hi_quad(pa[it]));
            STS64(base + ALO + ro, lo_quad(pa[it]));
            STS64(base + BHI + ro, hi_quad(pb[it]));
            STS64(base + BLO + ro, lo_quad(pb[it]));
        }
    }
    __syncthreads();

#pragma unroll 1
    for (int kb = 0; kb < NKB; kb++) {
        // prefetch next k-block (global -> regs), LDG issued before compute
        if (kb + 1 < NKB) {
            const int kq = (kb + 1) * 8 + lkq;
#pragma unroll
            for (int it = 0; it < 4; it++) {
                pa[it] = Apk[(size_t)(m0 + lrow + it * 32) * (EE / 4) + kq];
                pb[it] = Bpk[(size_t)(n0 + lrow + it * 32) * (EE / 4) + kq];
            }
        }

        const uint32_t base = sb + (uint32_t)(kb & 1) * BUF_B;
#pragma unroll
        for (int ks = 0; ks < 2; ks++) {
            const uint32_t ko = (uint32_t)ks * 32;   // 16 bf16 = 32 bytes
            uint32_t ah0[4], ah1[4], al0[4], al1[4];
            LDSM4(ah0, base + AHI + aoff0 + ko);
            LDSM4(ah1, base + AHI + aoff1 + ko);
            LDSM4(al0, base + ALO + aoff0 + ko);
            LDSM4(al1, base + ALO + aoff1 + ko);
#pragma unroll
            for (int np = 0; np < 4; np++) {
                uint32_t bh[4], bl[4];
                LDSM4(bh, base + BHI + boff[np] + ko);
                LDSM4(bl, base + BLO + boff[np] + ko);
                // 3-term split: ah*bh + ah*bl + al*bh
                mma_bf16(acc[0][np * 2],     ah0, bh[0], bh[1]);
                mma_bf16(acc[0][np * 2],     ah0, bl[0], bl[1]);
                mma_bf16(acc[0][np * 2],     al0, bh[0], bh[1]);
                mma_bf16(acc[0][np * 2 + 1], ah0, bh[2], bh[3]);
                mma_bf16(acc[0][np * 2 + 1], ah0, bl[2], bl[3]);
                mma_bf16(acc[0][np * 2 + 1], al0, bh[2], bh[3]);
                mma_bf16(acc[1][np * 2],     ah1, bh[0], bh[1]);
                mma_bf16(acc[1][np * 2],     ah1, bl[0], bl[1]);
                mma_bf16(acc[1][np * 2],     al1, bh[0], bh[1]);
                mma_bf16(acc[1][np * 2 + 1], ah1, bh[2], bh[3]);
                mma_bf16(acc[1][np * 2 + 1], ah1, bl[2], bl[3]);
                mma_bf16(acc[1][np * 2 + 1], al1, bh[2], bh[3]);
            }
        }

        // store prefetched block into the other buffer
        if (kb + 1 < NKB) {
            const uint32_t nbase = sb + (uint32_t)((kb + 1) & 1) * BUF_B;
            const uint32_t so = (uint32_t)(lrow * ROWB + lkq * 8);
#pragma unroll
            for (int it = 0; it < 4; it++) {
                uint32_t ro = so + it * 32 * ROWB;
                STS64(nbase + AHI + ro, hi_quad(pa[it]));
                STS64(nbase + ALO + ro, lo_quad(pa[it]));
                STS64(nbase + BHI + ro, hi_quad(pb[it]));
                STS64(nbase + BLO + ro, lo_quad(pb[it]));
            }
        }
        __syncthreads();
    }

    // ---- epilogue: bias + scale, direct float2 stores ----
    const int mbase = m0 + wy * 32 + (lane >> 2);
    const int nbase = n0 + wx * 64 + (lane & 3) * 2;
    float2 bb[8];
#pragma unroll
    for (int nf = 0; nf < 8; nf++)
        bb[nf] = *(const float2*)(bias + nbase + nf * 8);

#pragma unroll
    for (int mi = 0; mi < 2; mi++) {
#pragma unroll
        for (int rr = 0; rr < 2; rr++) {
            const int m = mbase + mi * 16 + rr * 8;
            float* crow = C + (size_t)m * EE;
#pragma unroll
            for (int nf = 0; nf < 8; nf++) {
                float2 v;
                v.x = (acc[mi][nf][rr * 2]     + bb[nf].x) * scale;
                v.y = (acc[mi][nf][rr * 2 + 1] + bb[nf].y) * scale;
                *(float2*)(crow + nbase + nf * 8) = v;
            }
        }
    }
}

// Stage 1: QKV projections. grid = (EE/BN=6, MTOK/BM=256, 3)
__global__ __launch_bounds__(256, 1) void qkv_mma_kernel(
    const float* __restrict__ bq, const float* __restrict__ bk,
    const float* __restrict__ bv)
{
    const int which = blockIdx.z;
    const uint4* B = (const uint4*)(g_wt + (size_t)which * EE * EE);
    const float* bias = (which == 0) ? bq : (which == 1) ? bk : bv;
    float* out = (which == 0) ? g_q : (which == 1) ? g_k : g_v;
    const float scale = (which == 0) ? QSCALE : 1.0f;
    gemm_mma_body((const uint4*)g_xp, B, bias, out, scale,
                  blockIdx.y * BM, blockIdx.x * BN);
}

// Stage 5: output projection. grid = (6, 256)
__global__ __launch_bounds__(256, 1) void out_mma_kernel(
    const float* __restrict__ bo, float* __restrict__ out)
{
    const uint4* B = (const uint4*)(g_wt + (size_t)3 * EE * EE);
    gemm_mma_body((const uint4*)g_ctxp, B, bo, out, 1.0f,
                  blockIdx.y * BM, blockIdx.x * BN);
}

// ---------------------------------------------------------------------------
// Stage 2: tied-row logits (SIMT fp32).
// logits[h,i,j] = sum_{r,d} q[r,i,h,d] * k[r,j,h,d]
// ---------------------------------------------------------------------------
__global__ __launch_bounds__(256) void logits_kernel()
{
    const int h  = blockIdx.z;
    const int i0 = blockIdx.y * 64;
    const int j0 = blockIdx.x * 64;

    __shared__ float Qs[16][64];
    __shared__ float Ks[16][64];

    const int tid = threadIdx.x;
    const int tx = tid & 15;
    const int ty = tid >> 4;
    const int lrow = tid >> 2;
    const int lcol = (tid & 3) * 4;

    float acc[4][4];
#pragma unroll
    for (int i = 0; i < 4; i++)
#pragma unroll
        for (int j = 0; j < 4; j++) acc[i][j] = 0.0f;

    for (int r = 0; r < RR; r++) {
        const float* qb = g_q + (size_t)(r * CC) * EE + h * DD;
        const float* kb = g_k + (size_t)(r * CC) * EE + h * DD;
#pragma unroll
        for (int d0 = 0; d0 < DD; d0 += 16) {
            float4 qv = *(const float4*)(qb + (size_t)(i0 + lrow) * EE + d0 + lcol);
            float4 kv = *(const float4*)(kb + (size_t)(j0 + lrow) * EE + d0 + lcol);
            Qs[lcol + 0][lrow] = qv.x; Qs[lcol + 1][lrow] = qv.y;
            Qs[lcol + 2][lrow] = qv.z; Qs[lcol + 3][lrow] = qv.w;
            Ks[lcol + 0][lrow] = kv.x; Ks[lcol + 1][lrow] = kv.y;
            Ks[lcol + 2][lrow] = kv.z; Ks[lcol + 3][lrow] = kv.w;
            __syncthreads();
#pragma unroll
            for (int k = 0; k < 16; k++) {
                float a[4], b[4];
                float4 av = *(const float4*)(&Qs[k][ty * 4]);
                float4 bv = *(const float4*)(&Ks[k][tx * 4]);
                a[0]=av.x; a[1]=av.y; a[2]=av.z; a[3]=av.w;
                b[0]=bv.x; b[1]=bv.y; b[2]=bv.z; b[3]=bv.w;
#pragma unroll
                for (int i = 0; i < 4; i++)
#pragma unroll
                    for (int j = 0; j < 4; j++)
                        acc[i][j] = fmaf(a[i], b[j], acc[i][j]);
            }
            __syncthreads();
        }
    }

    float* L = g_attn + (size_t)h * CC * CC;
#pragma unroll
    for (int i = 0; i < 4; i++) {
        float4 v;
        v.x = acc[i][0]; v.y = acc[i][1]; v.z = acc[i][2]; v.w = acc[i][3];
        *(float4*)(L + (size_t)(i0 + ty * 4 + i) * CC + j0 + tx * 4) = v;
    }
}

// ---------------------------------------------------------------------------
// Stage 3: softmax over rows of length 256, in place on g_attn.
// ---------------------------------------------------------------------------
__global__ __launch_bounds__(256) void softmax_kernel()
{
    float* p = g_attn + (size_t)blockIdx.x * CC;
    const int t = threadIdx.x;
    __shared__ float red[256];

    float v = p[t];
    red[t] = v;
    __syncthreads();
#pragma unroll
    for (int s = 128; s > 0; s >>= 1) {
        if (t < s) red[t] = fmaxf(red[t], red[t + s]);
        __syncthreads();
    }
    const float m = red[0];
    __syncthreads();

    const float e = __expf(v - m);
    red[t] = e;
    __syncthreads();
#pragma unroll
    for (int s = 128; s > 0; s >>= 1) {
        if (t < s) red[t] += red[t + s];
        __syncthreads();
    }
    p[t] = e / red[0];
}

// ---------------------------------------------------------------------------
// Stage 4: context (SIMT, writes packed split-bf16 for stage 5)
// ---------------------------------------------------------------------------
__global__ __launch_bounds__(256) void context_kernel()
{
    const int h  = blockIdx.z;
    const int r  = blockIdx.y;
    const int i0 = blockIdx.x * 64;

    __shared__ float Ps[16][64];
    __shared__ float Vs[16][64];

    const int tid = threadIdx.x;
    const int tx = tid & 15;
    const int ty = tid >> 4;
    const int prow = tid >> 2;
    const int pcol = (tid & 3) * 4;
    const int vrow = tid >> 4;
    const int vcol = (tid & 15) * 4;

    float acc[4][4];
#pragma unroll
    for (int i = 0; i < 4; i++)
#pragma unroll
        for (int j = 0; j < 4; j++) acc[i][j] = 0.0f;

    const float* P = g_attn + (size_t)h * CC * CC;
    const float* V = g_v + (size_t)(r * CC) * EE + h * DD;

    for (int j0 = 0; j0 < CC; j0 += 16) {
        float4 pv = *(const float4*)(P + (size_t)(i0 + prow) * CC + j0 + pcol);
        Ps[pcol + 0][prow] = pv.x; Ps[pcol + 1][prow] = pv.y;
        Ps[pcol + 2][prow] = pv.z; Ps[pcol + 3][prow] = pv.w;
        float4 vv = *(const float4*)(V + (size_t)(j0 + vrow) * EE + vcol);
        *(float4*)(&Vs[vrow][vcol]) = vv;
        __syncthreads();
#pragma unroll
        for (int k = 0; k < 16; k++) {
            float a[4], b[4];
            float4 av = *(const float4*)(&Ps[k][ty * 4]);
            float4 bv = *(const float4*)(&Vs[k][tx * 4]);
            a[0]=av.x; a[1]=av.y; a[2]=av.z; a[3]=av.w;
            b[0]=bv.x; b[1]=bv.y; b[2]=bv.z; b[3]=bv.w;
#pragma unroll
            for (int i = 0; i < 4; i++)
#pragma unroll
                for (int j = 0; j < 4; j++)
                    acc[i][j] = fmaf(a[i], b[j], acc[i][j]);
        }
        __syncthreads();
    }

#pragma unroll
    for (int i = 0; i < 4; i++) {
        uint4 pvo;
        pvo.x = pack_bf16_split(acc[i][0]);
        pvo.y = pack_bf16_split(acc[i][1]);
        pvo.z = pack_bf16_split(acc[i][2]);
        pvo.w = pack_bf16_split(acc[i][3]);
        *(uint4*)(g_ctxp + (size_t)(r * CC + i0 + ty * 4 + i) * EE + h * DD + tx * 4) = pvo;
    }
}

// ---------------------------------------------------------------------------
extern "C" void kernel_launch(void* const* d_in, const int* in_sizes, int n_in,
                              void* d_out, int out_size)
{
    (void)in_sizes; (void)n_in; (void)out_size;
    const float* x  = (const float*)d_in[0];
    const float* wq = (const float*)d_in[1];
    const float* bq = (const float*)d_in[2];
    const float* wk = (const float*)d_in[3];
    const float* bk = (const float*)d_in[4];
    const float* wv = (const float*)d_in[5];
    const float* bv = (const float*)d_in[6];
    const float* wo = (const float*)d_in[7];
    const float* bo = (const float*)d_in[8];
    float* out = (float*)d_out;

    static int smem_configured = 0;
    if (!smem_configured) {
        cudaFuncSetAttribute(qkv_mma_kernel,
                             cudaFuncAttributeMaxDynamicSharedMemorySize, SMEM_TOTAL);
        cudaFuncSetAttribute(out_mma_kernel,
                             cudaFuncAttributeMaxDynamicSharedMemorySize, SMEM_TOTAL);
        smem_configured = 1;
    }

    // Pack inputs into split-bf16
    pack_x_kernel<<<(MTOK * EE / 4) / 256, 256>>>(x);
    dim3 gw(EE / 32, EE / 32, 4);
    pack_wt_kernel<<<gw, 256>>>(wq, wk, wv, wo);

    // Stage 1: QKV projections (mma.sync split-bf16)
    dim3 g1(EE / BN, MTOK / BM, 3);               // (6, 256, 3)
    qkv_mma_kernel<<<g1, 256, SMEM_TOTAL>>>(bq, bk, bv);

    // Stage 2: tied logits
    dim3 g2(CC / 64, CC / 64, HH);                // (4, 4, 12)
    logits_kernel<<<g2, 256>>>();

    // Stage 3: softmax
    softmax_kernel<<<HH * CC, 256>>>();

    // Stage 4: context (writes packed split-bf16)
    dim3 g4(CC / 64, RR, HH);                     // (4, 128, 12)
    context_kernel<<<g4, 256>>>();

    // Stage 5: output projection (mma.sync split-bf16)
    dim3 g5(EE / BN, MTOK / BM, 1);               // (6, 256)
    out_mma_kernel<<<g5, 256, SMEM_TOTAL>>>(bo, out);
}

// round 9
// speedup vs baseline: 2.8528x; 1.4949x over previous
#include <cuda_runtime.h>
#include <cuda_bf16.h>
#include <stdint.h>
#include <math.h>

// ---------------------------------------------------------------------------
// Problem constants
// ---------------------------------------------------------------------------
#define RR 128
#define CC 256
#define EE 768
#define HH 12
#define DD 64
#define MTOK (RR * CC)            // 32768 tokens
#define QSCALE (0.0110485434560398f)   // (1/8) / sqrt(128)
#define RSPLIT 8                  // split-K chunks over r for logits
#define RCHUNK (RR / RSPLIT)      // 16

// ---------------------------------------------------------------------------
// mma.sync GEMM tiling (stages 1 & 5): CTA 128x128, BK=32, 8 warps (4M x 2N)
// ---------------------------------------------------------------------------
#define BM 128
#define BN 128
#define BK 32
#define NKB (EE / BK)             // 24
#define KPAD 40                   // bf16 elems per smem row (32 + 8 pad) = 80 B
#define ROWB (KPAD * 2)           // 80 bytes per row
#define TILE_B (BM * ROWB)        // 10240 bytes per (hi or lo) tile
#define AHI 0
#define ALO TILE_B
#define BHI (2 * TILE_B)
#define BLO (3 * TILE_B)
#define BUF_B (4 * TILE_B)        // 40960 bytes per k-block buffer
#define SMEM_TOTAL (2 * BUF_B)    // 81920 bytes

// context kernel smem: P tile 128x32 (hi/lo, ROWB rows) + V tile 32x64 (hi/lo)
#define VROWB 144                 // 64 bf16 = 128 B + 16 pad
#define CPTILE (128 * ROWB)       // 10240
#define CVTILE (32 * VROWB)       // 4608
#define CPHI 0
#define CPLO CPTILE
#define CVHI (2 * CPTILE)
#define CVLO (2 * CPTILE + CVTILE)
#define CBUF_B (2 * CPTILE + 2 * CVTILE)   // 29696
#define CSMEM_TOTAL (2 * CBUF_B)           // 59392

// ---------------------------------------------------------------------------
// Device global scratch (allocation-free per harness rules)
// ---------------------------------------------------------------------------
__device__ uint32_t g_xp[(size_t)MTOK * EE];     // x packed (hi bf16 | lo bf16<<16)
__device__ uint32_t g_wt[4 * (size_t)EE * EE];   // transposed packed weights [n][k]
__device__ uint32_t g_qp[(size_t)MTOK * EE];     // q packed (scaled, biased)
__device__ uint32_t g_kp[(size_t)MTOK * EE];     // k packed
__device__ uint32_t g_vp[(size_t)MTOK * EE];     // v packed
__device__ uint32_t g_ctxp[(size_t)MTOK * EE];   // context packed
__device__ float    g_lpart[(size_t)RSPLIT * HH * CC * CC];  // logits partials
__device__ uint32_t g_attnp[(size_t)HH * CC * CC];           // probs packed

// ---------------------------------------------------------------------------
// Helpers
// ---------------------------------------------------------------------------
__device__ __forceinline__ uint32_t smem_to_u32(const void* p) {
    uint32_t a;
    asm("{ .reg .u64 t; cvta.to.shared.u64 t, %1; cvt.u32.u64 %0, t; }"
        : "=r"(a) : "l"(p));
    return a;
}

#define STS64(addr, val) \
    asm volatile("st.shared.b64 [%0], %1;" :: "r"(addr), "l"(val) : "memory")

#define LDSM4(r, addr) \
    asm volatile("ldmatrix.sync.aligned.m8n8.x4.shared.b16 {%0,%1,%2,%3}, [%4];" \
        : "=r"((r)[0]), "=r"((r)[1]), "=r"((r)[2]), "=r"((r)[3]) : "r"(addr))

#define LDSM4T(r, addr) \
    asm volatile("ldmatrix.sync.aligned.m8n8.x4.trans.shared.b16 {%0,%1,%2,%3}, [%4];" \
        : "=r"((r)[0]), "=r"((r)[1]), "=r"((r)[2]), "=r"((r)[3]) : "r"(addr))

__device__ __forceinline__ void mma_bf16(float* c, const uint32_t* a,
                                         uint32_t b0, uint32_t b1) {
    asm volatile(
        "mma.sync.aligned.m16n8k16.row.col.f32.bf16.bf16.f32 "
        "{%0,%1,%2,%3}, {%4,%5,%6,%7}, {%8,%9}, {%0,%1,%2,%3};"
        : "+f"(c[0]), "+f"(c[1]), "+f"(c[2]), "+f"(c[3])
        : "r"(a[0]), "r"(a[1]), "r"(a[2]), "r"(a[3]), "r"(b0), "r"(b1));
}

// split-bf16 packing: low 16 bits = hi bf16, high 16 bits = lo bf16
__device__ __forceinline__ uint32_t pack_bf16_split(float f) {
    __nv_bfloat16 h = __float2bfloat16(f);
    float r = f - __bfloat162float(h);
    __nv_bfloat16 l = __float2bfloat16(r);
    return (uint32_t)__bfloat16_as_ushort(h) | ((uint32_t)__bfloat16_as_ushort(l) << 16);
}

__device__ __forceinline__ uint64_t hi_quad(uint4 v) {
    uint32_t h01 = __byte_perm(v.x, v.y, 0x5410);
    uint32_t h23 = __byte_perm(v.z, v.w, 0x5410);
    return (uint64_t)h01 | ((uint64_t)h23 << 32);
}
__device__ __forceinline__ uint64_t lo_quad(uint4 v) {
    uint32_t l01 = __byte_perm(v.x, v.y, 0x7632);
    uint32_t l23 = __byte_perm(v.z, v.w, 0x7632);
    return (uint64_t)l01 | ((uint64_t)l23 << 32);
}

// ---------------------------------------------------------------------------
// Pack kernels
// ---------------------------------------------------------------------------
__global__ __launch_bounds__(256) void pack_x_kernel(const float* __restrict__ x)
{
    size_t idx = (size_t)blockIdx.x * 256 + threadIdx.x;
    float4 v = ((const float4*)x)[idx];
    uint4 o;
    o.x = pack_bf16_split(v.x);
    o.y = pack_bf16_split(v.y);
    o.z = pack_bf16_split(v.z);
    o.w = pack_bf16_split(v.w);
    ((uint4*)g_xp)[idx] = o;
}

__global__ __launch_bounds__(256) void pack_wt_kernel(
    const float* __restrict__ wq, const float* __restrict__ wk,
    const float* __restrict__ wv, const float* __restrict__ wo)
{
    const int mat = blockIdx.z;
    const float* W = (mat == 0) ? wq : (mat == 1) ? wk : (mat == 2) ? wv : wo;
    __shared__ float s[32][33];
    const int k0 = blockIdx.y * 32, n0 = blockIdx.x * 32;
    const int tx = threadIdx.x & 31, ty = threadIdx.x >> 5;
#pragma unroll
    for (int i = 0; i < 32; i += 8)
        s[ty + i][tx] = W[(size_t)(k0 + ty + i) * EE + n0 + tx];
    __syncthreads();
    uint32_t* dst = g_wt + (size_t)mat * EE * EE;
#pragma unroll
    for (int i = 0; i < 32; i += 8)
        dst[(size_t)(n0 + ty + i) * EE + k0 + tx] = pack_bf16_split(s[tx][ty + i]);
}

// ---------------------------------------------------------------------------
// Split-bf16 mma.sync GEMM core (stages 1 & 5).
//   A packed [M x 768] row-major, Bt packed [768(n) x 768(k)] row-major.
//   out = (A @ Bt^T + bias) * scale. PACK selects packed-uint32 vs fp32 output.
// ---------------------------------------------------------------------------
template<bool PACK>
__device__ void gemm_mma_body(
    const uint4* __restrict__ Apk, const uint4* __restrict__ Bpk,
    const float* __restrict__ bias, void* __restrict__ Cout,
    float scale, int m0, int n0)
{
    extern __shared__ char smem[];
    const uint32_t sb = smem_to_u32(smem);
    const int tid  = threadIdx.x;
    const int lane = tid & 31;
    const int w    = tid >> 5;
    const int wy   = w & 3;
    const int wx   = w >> 2;

    const int lrow = tid >> 3;
    const int lkq  = tid & 7;

    const uint32_t aoff0 = (uint32_t)((wy * 32 + (lane & 15)) * ROWB + ((lane >> 4) * 8) * 2);
    const uint32_t aoff1 = aoff0 + 16 * ROWB;
    const uint32_t brow  = (uint32_t)(wx * 64 + ((lane >> 4) & 1) * 8 + (lane & 7));
    const uint32_t bkc   = (uint32_t)(((lane >> 3) & 1) * 8) * 2;
    uint32_t boff[4];
#pragma unroll
    for (int np = 0; np < 4; np++)
        boff[np] = (brow + np * 16) * ROWB + bkc;

    float acc[2][8][4];
#pragma unroll
    for (int mi = 0; mi < 2; mi++)
#pragma unroll
        for (int nf = 0; nf < 8; nf++)
#pragma unroll
            for (int r = 0; r < 4; r++) acc[mi][nf][r] = 0.0f;

    uint4 pa[4], pb[4];
#pragma unroll
    for (int it = 0; it < 4; it++) {
        pa[it] = Apk[(size_t)(m0 + lrow + it * 32) * (EE / 4) + lkq];
        pb[it] = Bpk[(size_t)(n0 + lrow + it * 32) * (EE / 4) + lkq];
    }
    {
        const uint32_t base = sb;
        const uint32_t so = (uint32_t)(lrow * ROWB + lkq * 8);
#pragma unroll
        for (int it = 0; it < 4; it++) {
            uint32_t ro = so + it * 32 * ROWB;
            STS64(base + AHI + ro, hi_quad(pa[it]));
            STS64(base + ALO + ro, lo_quad(pa[it]));
            STS64(base + BHI + ro, hi_quad(pb[it]));
            STS64(base + BLO + ro, lo_quad(pb[it]));
        }
    }
    __syncthreads();

#pragma unroll 1
    for (int kb = 0; kb < NKB; kb++) {
        if (kb + 1 < NKB) {
            const int kq = (kb + 1) * 8 + lkq;
#pragma unroll
            for (int it = 0; it < 4; it++) {
                pa[it] = Apk[(size_t)(m0 + lrow + it * 32) * (EE / 4) + kq];
                pb[it] = Bpk[(size_t)(n0 + lrow + it * 32) * (EE / 4) + kq];
            }
        }

        const uint32_t base = sb + (uint32_t)(kb & 1) * BUF_B;
#pragma unroll
        for (int ks = 0; ks < 2; ks++) {
            const uint32_t ko = (uint32_t)ks * 32;
            uint32_t ah0[4], ah1[4], al0[4], al1[4];
            LDSM4(ah0, base + AHI + aoff0 + ko);
            LDSM4(ah1, base + AHI + aoff1 + ko);
            LDSM4(al0, base + ALO + aoff0 + ko);
            LDSM4(al1, base + ALO + aoff1 + ko);
#pragma unroll
            for (int np = 0; np < 4; np++) {
                uint32_t bh[4], bl[4];
                LDSM4(bh, base + BHI + boff[np] + ko);
                LDSM4(bl, base + BLO + boff[np] + ko);
                mma_bf16(acc[0][np * 2],     ah0, bh[0], bh[1]);
                mma_bf16(acc[0][np * 2],     ah0, bl[0], bl[1]);
                mma_bf16(acc[0][np * 2],     al0, bh[0], bh[1]);
                mma_bf16(acc[0][np * 2 + 1], ah0, bh[2], bh[3]);
                mma_bf16(acc[0][np * 2 + 1], ah0, bl[2], bl[3]);
                mma_bf16(acc[0][np * 2 + 1], al0, bh[2], bh[3]);
                mma_bf16(acc[1][np * 2],     ah1, bh[0], bh[1]);
                mma_bf16(acc[1][np * 2],     ah1, bl[0], bl[1]);
                mma_bf16(acc[1][np * 2],     al1, bh[0], bh[1]);
                mma_bf16(acc[1][np * 2 + 1], ah1, bh[2], bh[3]);
                mma_bf16(acc[1][np * 2 + 1], ah1, bl[2], bl[3]);
                mma_bf16(acc[1][np * 2 + 1], al1, bh[2], bh[3]);
            }
        }

        if (kb + 1 < NKB) {
            const uint32_t nbase = sb + (uint32_t)((kb + 1) & 1) * BUF_B;
            const uint32_t so = (uint32_t)(lrow * ROWB + lkq * 8);
#pragma unroll
            for (int it = 0; it < 4; it++) {
                uint32_t ro = so + it * 32 * ROWB;
                STS64(nbase + AHI + ro, hi_quad(pa[it]));
                STS64(nbase + ALO + ro, lo_quad(pa[it]));
                STS64(nbase + BHI + ro, hi_quad(pb[it]));
                STS64(nbase + BLO + ro, lo_quad(pb[it]));
            }
        }
        __syncthreads();
    }

    const int mbase = m0 + wy * 32 + (lane >> 2);
    const int nbase = n0 + wx * 64 + (lane & 3) * 2;
    float2 bb[8];
#pragma unroll
    for (int nf = 0; nf < 8; nf++)
        bb[nf] = *(const float2*)(bias + nbase + nf * 8);

#pragma unroll
    for (int mi = 0; mi < 2; mi++) {
#pragma unroll
        for (int rr = 0; rr < 2; rr++) {
            const int m = mbase + mi * 16 + rr * 8;
#pragma unroll
            for (int nf = 0; nf < 8; nf++) {
                float v0 = (acc[mi][nf][rr * 2]     + bb[nf].x) * scale;
                float v1 = (acc[mi][nf][rr * 2 + 1] + bb[nf].y) * scale;
                if (PACK) {
                    uint2 u;
                    u.x = pack_bf16_split(v0);
                    u.y = pack_bf16_split(v1);
                    *(uint2*)((uint32_t*)Cout + (size_t)m * EE + nbase + nf * 8) = u;
                } else {
                    float2 v; v.x = v0; v.y = v1;
                    *(float2*)((float*)Cout + (size_t)m * EE + nbase + nf * 8) = v;
                }
            }
        }
    }
}

// Stage 1: QKV projections -> packed. grid = (6, 256, 3)
__global__ __launch_bounds__(256, 1) void qkv_mma_kernel(
    const float* __restrict__ bq, const float* __restrict__ bk,
    const float* __restrict__ bv)
{
    const int which = blockIdx.z;
    const uint4* B = (const uint4*)(g_wt + (size_t)which * EE * EE);
    const float* bias = (which == 0) ? bq : (which == 1) ? bk : bv;
    uint32_t* out = (which == 0) ? g_qp : (which == 1) ? g_kp : g_vp;
    const float scale = (which == 0) ? QSCALE : 1.0f;
    gemm_mma_body<true>((const uint4*)g_xp, B, bias, out, scale,
                        blockIdx.y * BM, blockIdx.x * BN);
}

// Stage 5: output projection -> fp32. grid = (6, 256)
__global__ __launch_bounds__(256, 1) void out_mma_kernel(
    const float* __restrict__ bo, float* __restrict__ out)
{
    const uint4* B = (const uint4*)(g_wt + (size_t)3 * EE * EE);
    gemm_mma_body<false>((const uint4*)g_ctxp, B, bo, out, 1.0f,
                         blockIdx.y * BM, blockIdx.x * BN);
}

// ---------------------------------------------------------------------------
// Stage 2: tied-row logits on tensor cores, split-K over r.
// partial[rs][h][i][j] = sum_{r in chunk rs, d} q[r,i,h,d]*k[r,j,h,d]
// grid = (4 tiles, HH, RSPLIT), 256 threads.
// ---------------------------------------------------------------------------
__global__ __launch_bounds__(256, 1) void logits_mma_kernel()
{
    const int h  = blockIdx.y;
    const int r0 = blockIdx.z * RCHUNK;
    const int m0 = (blockIdx.x >> 1) * 128;   // i tile
    const int n0 = (blockIdx.x & 1) * 128;    // j tile
    const int NKK = RCHUNK * 2;               // 32 k-blocks of 32 (K = 1024)

    extern __shared__ char smem[];
    const uint32_t sb = smem_to_u32(smem);
    const int tid  = threadIdx.x;
    const int lane = tid & 31;
    const int w    = tid >> 5;
    const int wy   = w & 3;
    const int wx   = w >> 2;
    const int lrow = tid >> 3;
    const int lkq  = tid & 7;

    const uint4* Aq = (const uint4*)g_qp;
    const uint4* Bk = (const uint4*)g_kp;

    const uint32_t aoff0 = (uint32_t)((wy * 32 + (lane & 15)) * ROWB + ((lane >> 4) * 8) * 2);
    const uint32_t aoff1 = aoff0 + 16 * ROWB;
    const uint32_t brow  = (uint32_t)(wx * 64 + ((lane >> 4) & 1) * 8 + (lane & 7));
    const uint32_t bkc   = (uint32_t)(((lane >> 3) & 1) * 8) * 2;
    uint32_t boff[4];
#pragma unroll
    for (int np = 0; np < 4; np++)
        boff[np] = (brow + np * 16) * ROWB + bkc;

    float acc[2][8][4];
#pragma unroll
    for (int mi = 0; mi < 2; mi++)
#pragma unroll
        for (int nf = 0; nf < 8; nf++)
#pragma unroll
            for (int r = 0; r < 4; r++) acc[mi][nf][r] = 0.0f;

    // global address for (row, kk):  (r0+(kk>>1))*CC + row  over d-half kk&1
    uint4 pa[4], pb[4];
#pragma unroll
    for (int it = 0; it < 4; it++) {
        pa[it] = Aq[(size_t)(r0 * CC + m0 + lrow + it * 32) * (EE / 4) + h * 16 + lkq];
        pb[it] = Bk[(size_t)(r0 * CC + n0 + lrow + it * 32) * (EE / 4) + h * 16 + lkq];
    }
    {
        const uint32_t base = sb;
        const uint32_t so = (uint32_t)(lrow * ROWB + lkq * 8);
#pragma unroll
        for (int it = 0; it < 4; it++) {
            uint32_t ro = so + it * 32 * ROWB;
            STS64(base + AHI + ro, hi_quad(pa[it]));
            STS64(base + ALO + ro, lo_quad(pa[it]));
            STS64(base + BHI + ro, hi_quad(pb[it]));
            STS64(base + BLO + ro, lo_quad(pb[it]));
        }
    }
    __syncthreads();

#pragma unroll 1
    for (int kk = 0; kk < NKK; kk++) {
        if (kk + 1 < NKK) {
            const int r  = r0 + ((kk + 1) >> 1);
            const int kb = (kk + 1) & 1;
#pragma unroll
            for (int it = 0; it < 4; it++) {
                pa[it] = Aq[(size_t)(r * CC + m0 + lrow + it * 32) * (EE / 4) + h * 16 + kb * 8 + lkq];
                pb[it] = Bk[(size_t)(r * CC + n0 + lrow + it * 32) * (EE / 4) + h * 16 + kb * 8 + lkq];
            }
        }

        const uint32_t base = sb + (uint32_t)(kk & 1) * BUF_B;
#pragma unroll
        for (int ks = 0; ks < 2; ks++) {
            const uint32_t ko = (uint32_t)ks * 32;
            uint32_t ah0[4], ah1[4], al0[4], al1[4];
            LDSM4(ah0, base + AHI + aoff0 + ko);
            LDSM4(ah1, base + AHI + aoff1 + ko);
            LDSM4(al0, base + ALO + aoff0 + ko);
            LDSM4(al1, base + ALO + aoff1 + ko);
#pragma unroll
            for (int np = 0; np < 4; np++) {
                uint32_t bh[4], bl[4];
                LDSM4(bh, base + BHI + boff[np] + ko);
                LDSM4(bl, base + BLO + boff[np] + ko);
                mma_bf16(acc[0][np * 2],     ah0, bh[0], bh[1]);
                mma_bf16(acc[0][np * 2],     ah0, bl[0], bl[1]);
                mma_bf16(acc[0][np * 2],     al0, bh[0], bh[1]);
                mma_bf16(acc[0][np * 2 + 1], ah0, bh[2], bh[3]);
                mma_bf16(acc[0][np * 2 + 1], ah0, bl[2], bl[3]);
                mma_bf16(acc[0][np * 2 + 1], al0, bh[2], bh[3]);
                mma_bf16(acc[1][np * 2],     ah1, bh[0], bh[1]);
                mma_bf16(acc[1][np * 2],     ah1, bl[0], bl[1]);
                mma_bf16(acc[1][np * 2],     al1, bh[0], bh[1]);
                mma_bf16(acc[1][np * 2 + 1], ah1, bh[2], bh[3]);
                mma_bf16(acc[1][np * 2 + 1], ah1, bl[2], bl[3]);
                mma_bf16(acc[1][np * 2 + 1], al1, bh[2], bh[3]);
            }
        }

        if (kk + 1 < NKK) {
            const uint32_t nbase = sb + (uint32_t)((kk + 1) & 1) * BUF_B;
            const uint32_t so = (uint32_t)(lrow * ROWB + lkq * 8);
#pragma unroll
            for (int it = 0; it < 4; it++) {
                uint32_t ro = so + it * 32 * ROWB;
                STS64(nbase + AHI + ro, hi_quad(pa[it]));
                STS64(nbase + ALO + ro, lo_quad(pa[it]));
                STS64(nbase + BHI + ro, hi_quad(pb[it]));
                STS64(nbase + BLO + ro, lo_quad(pb[it]));
            }
        }
        __syncthreads();
    }

    // epilogue: raw partial sums
    float* P = g_lpart + ((size_t)blockIdx.z * HH + h) * CC * CC;
    const int mbase = m0 + wy * 32 + (lane >> 2);
    const int nbase = n0 + wx * 64 + (lane & 3) * 2;
#pragma unroll
    for (int mi = 0; mi < 2; mi++) {
#pragma unroll
        for (int rr = 0; rr < 2; rr++) {
            const int m = mbase + mi * 16 + rr * 8;
#pragma unroll
            for (int nf = 0; nf < 8; nf++) {
                float2 v;
                v.x = acc[mi][nf][rr * 2];
                v.y = acc[mi][nf][rr * 2 + 1];
                *(float2*)(P + (size_t)m * CC + nbase + nf * 8) = v;
            }
        }
    }
}

// ---------------------------------------------------------------------------
// Stage 3: split-K reduce + softmax + pack.  grid = HH*CC rows of 256.
// ---------------------------------------------------------------------------
__global__ __launch_bounds__(256) void softmax_kernel()
{
    const size_t row = blockIdx.x;     // h*CC + i
    const int t = threadIdx.x;
    __shared__ float red[256];

    float v = 0.0f;
#pragma unroll
    for (int rs = 0; rs < RSPLIT; rs++)
        v += g_lpart[((size_t)rs * HH * CC + row) * CC + t];

    red[t] = v;
    __syncthreads();
#pragma unroll
    for (int s = 128; s > 0; s >>= 1) {
        if (t < s) red[t] = fmaxf(red[t], red[t + s]);
        __syncthreads();
    }
    const float m = red[0];
    __syncthreads();

    const float e = __expf(v - m);
    red[t] = e;
    __syncthreads();
#pragma unroll
    for (int s = 128; s > 0; s >>= 1) {
        if (t < s) red[t] += red[t + s];
        __syncthreads();
    }
    g_attnp[row * CC + t] = pack_bf16_split(e / red[0]);
}

// ---------------------------------------------------------------------------
// Stage 4: context on tensor cores.
// ctx[r,i,h,d] = sum_j P[h,i,j] * v[r,j,h,d]
// grid = (2 i-tiles, RR, HH), 256 threads. CTA: 128(i) x 64(d) x 256(j).
// ---------------------------------------------------------------------------
__global__ __launch_bounds__(256, 1) void context_mma_kernel()
{
    const int h  = blockIdx.z;
    const int r  = blockIdx.y;
    const int i0 = blockIdx.x * 128;
    const int NJB = CC / BK;           // 8 j-blocks

    extern __shared__ char smem[];
    const uint32_t sb = smem_to_u32(smem);
    const int tid  = threadIdx.x;
    const int lane = tid & 31;
    const int w    = tid >> 5;
    const int wy   = w & 3;            // m warp: i offset wy*32
    const int wx   = w >> 2;           // n warp: d offset wx*32

    const int lrow = tid >> 3;         // P loads: 0..31
    const int lkq  = tid & 7;
    const int vr   = tid >> 4;         // V loads: j row 0..15 (+16)
    const int cv   = tid & 15;         // uint4 col within 64 d

    const uint4* Pp = (const uint4*)(g_attnp + (size_t)h * CC * CC);
    const uint4* Vp = (const uint4*)g_vp;

    // A (P) ldmatrix offsets
    const uint32_t aoff0 = (uint32_t)((wy * 32 + (lane & 15)) * ROWB + ((lane >> 4) * 8) * 2);
    const uint32_t aoff1 = aoff0 + 16 * ROWB;
    // B (V) trans ldmatrix per-lane base: row=(mi&1)*8+wi, colbyte=(mi>>1)*16
    const uint32_t mi_ = (uint32_t)(lane >> 3);
    const uint32_t wi_ = (uint32_t)(lane & 7);
    const uint32_t vlb = ((mi_ & 1) * 8 + wi_) * VROWB + ((mi_ >> 1) * 8) * 2 + (uint32_t)(wx * 32) * 2;

    float acc[2][4][4];
#pragma unroll
    for (int mi = 0; mi < 2; mi++)
#pragma unroll
        for (int nf = 0; nf < 4; nf++)
#pragma unroll
            for (int q = 0; q < 4; q++) acc[mi][nf][q] = 0.0f;

    uint4 pa[4], pb[2];
#pragma unroll
    for (int it = 0; it < 4; it++)
        pa[it] = Pp[(size_t)(i0 + lrow + it * 32) * (CC / 4) + lkq];
#pragma unroll
    for (int it = 0; it < 2; it++)
        pb[it] = Vp[(size_t)(r * CC + vr + it * 16) * (EE / 4) + h * 16 + cv];
    {
        const uint32_t base = sb;
        const uint32_t soA = (uint32_t)(lrow * ROWB + lkq * 8);
#pragma unroll
        for (int it = 0; it < 4; it++) {
            uint32_t ro = soA + it * 32 * ROWB;
            STS64(base + CPHI + ro, hi_quad(pa[it]));
            STS64(base + CPLO + ro, lo_quad(pa[it]));
        }
        const uint32_t soV = (uint32_t)(vr * VROWB + cv * 8);
#pragma unroll
        for (int it = 0; it < 2; it++) {
            uint32_t ro = soV + it * 16 * VROWB;
            STS64(base + CVHI + ro, hi_quad(pb[it]));
            STS64(base + CVLO + ro, lo_quad(pb[it]));
        }
    }
    __syncthreads();

#pragma unroll 1
    for (int jb = 0; jb < NJB; jb++) {
        if (jb + 1 < NJB) {
            const int jq = (jb + 1) * 8 + lkq;
#pragma unroll
            for (int it = 0; it < 4; it++)
                pa[it] = Pp[(size_t)(i0 + lrow + it * 32) * (CC / 4) + jq];
            const int jrow = (jb + 1) * 32;
#pragma unroll
            for (int it = 0; it < 2; it++)
                pb[it] = Vp[(size_t)(r * CC + jrow + vr + it * 16) * (EE / 4) + h * 16 + cv];
        }

        const uint32_t base = sb + (uint32_t)(jb & 1) * CBUF_B;
#pragma unroll
        for (int ks = 0; ks < 2; ks++) {
            const uint32_t ko = (uint32_t)ks * 32;       // A: 16 elems * 2B
            const uint32_t kv = (uint32_t)ks * 16 * VROWB;
            uint32_t ah0[4], ah1[4], al0[4], al1[4];
            LDSM4(ah0, base + CPHI + aoff0 + ko);
            LDSM4(ah1, base + CPHI + aoff1 + ko);
            LDSM4(al0, base + CPLO + aoff0 + ko);
            LDSM4(al1, base + CPLO + aoff1 + ko);
#pragma unroll
            for (int np = 0; np < 2; np++) {
                uint32_t bh[4], bl[4];
                const uint32_t va = vlb + kv + (uint32_t)(np * 16) * 2;
                LDSM4T(bh, base + CVHI + va);
                LDSM4T(bl, base + CVLO + va);
                mma_bf16(acc[0][np * 2],     ah0, bh[0], bh[1]);
                mma_bf16(acc[0][np * 2],     ah0, bl[0], bl[1]);
                mma_bf16(acc[0][np * 2],     al0, bh[0], bh[1]);
                mma_bf16(acc[0][np * 2 + 1], ah0, bh[2], bh[3]);
                mma_bf16(acc[0][np * 2 + 1], ah0, bl[2], bl[3]);
                mma_bf16(acc[0][np * 2 + 1], al0, bh[2], bh[3]);
                mma_bf16(acc[1][np * 2],     ah1, bh[0], bh[1]);
                mma_bf16(acc[1][np * 2],     ah1, bl[0], bl[1]);
                mma_bf16(acc[1][np * 2],     al1, bh[0], bh[1]);
                mma_bf16(acc[1][np * 2 + 1], ah1, bh[2], bh[3]);
                mma_bf16(acc[1][np * 2 + 1], ah1, bl[2], bl[3]);
                mma_bf16(acc[1][np * 2 + 1], al1, bh[2], bh[3]);
            }
        }

        if (jb + 1 < NJB) {
            const uint32_t nbase = sb + (uint32_t)((jb + 1) & 1) * CBUF_B;
            const uint32_t soA = (uint32_t)(lrow * ROWB + lkq * 8);
#pragma unroll
            for (int it = 0; it < 4; it++) {
                uint32_t ro = soA + it * 32 * ROWB;
                STS64(nbase + CPHI + ro, hi_quad(pa[it]));
                STS64(nbase + CPLO + ro, lo_quad(pa[it]));
            }
            const uint32_t soV = (uint32_t)(vr * VROWB + cv * 8);
#pragma unroll
            for (int it = 0; it < 2; it++) {
                uint32_t ro = soV + it * 16 * VROWB;
                STS64(nbase + CVHI + ro, hi_quad(pb[it]));
                STS64(nbase + CVLO + ro, lo_quad(pb[it]));
            }
        }
        __syncthreads();
    }

    // epilogue: pack and store ctx[(r*CC+i)*EE + h*64 + d]
    const int mbase = i0 + wy * 32 + (lane >> 2);
    const int dbase = wx * 32 + (lane & 3) * 2;
#pragma unroll
    for (int mi = 0; mi < 2; mi++) {
#pragma unroll
        for (int rr = 0; rr < 2; rr++) {
            const int i = mbase + mi * 16 + rr * 8;
            uint32_t* crow = g_ctxp + (size_t)(r * CC + i) * EE + h * DD;
#pragma unroll
            for (int nf = 0; nf < 4; nf++) {
                uint2 u;
                u.x = pack_bf16_split(acc[mi][nf][rr * 2]);
                u.y = pack_bf16_split(acc[mi][nf][rr * 2 + 1]);
                *(uint2*)(crow + dbase + nf * 8) = u;
            }
        }
    }
}

// ---------------------------------------------------------------------------
extern "C" void kernel_launch(void* const* d_in, const int* in_sizes, int n_in,
                              void* d_out, int out_size)
{
    (void)in_sizes; (void)n_in; (void)out_size;
    const float* x  = (const float*)d_in[0];
    const float* wq = (const float*)d_in[1];
    const float* bq = (const float*)d_in[2];
    const float* wk = (const float*)d_in[3];
    const float* bk = (const float*)d_in[4];
    const float* wv = (const float*)d_in[5];
    const float* bv = (const float*)d_in[6];
    const float* wo = (const float*)d_in[7];
    const float* bo = (const float*)d_in[8];
    float* out = (float*)d_out;

    static int smem_configured = 0;
    if (!smem_configured) {
        cudaFuncSetAttribute(qkv_mma_kernel,
                             cudaFuncAttributeMaxDynamicSharedMemorySize, SMEM_TOTAL);
        cudaFuncSetAttribute(out_mma_kernel,
                             cudaFuncAttributeMaxDynamicSharedMemorySize, SMEM_TOTAL);
        cudaFuncSetAttribute(logits_mma_kernel,
                             cudaFuncAttributeMaxDynamicSharedMemorySize, SMEM_TOTAL);
        cudaFuncSetAttribute(context_mma_kernel,
                             cudaFuncAttributeMaxDynamicSharedMemorySize, CSMEM_TOTAL);
        smem_configured = 1;
    }

    // Pack inputs into split-bf16
    pack_x_kernel<<<(MTOK * EE / 4) / 256, 256>>>(x);
    dim3 gw(EE / 32, EE / 32, 4);
    pack_wt_kernel<<<gw, 256>>>(wq, wk, wv, wo);

    // Stage 1: QKV projections (packed output)
    dim3 g1(EE / BN, MTOK / BM, 3);               // (6, 256, 3)
    qkv_mma_kernel<<<g1, 256, SMEM_TOTAL>>>(bq, bk, bv);

    // Stage 2: tied logits, split-K partials
    dim3 g2(4, HH, RSPLIT);                       // (4, 12, 8) = 384 CTAs
    logits_mma_kernel<<<g2, 256, SMEM_TOTAL>>>();

    // Stage 3: reduce + softmax + pack
    softmax_kernel<<<HH * CC, 256>>>();

    // Stage 4: context (tensor cores, packed output)
    dim3 g4(CC / BM, RR, HH);                     // (2, 128, 12) = 3072 CTAs
    context_mma_kernel<<<g4, 256, CSMEM_TOTAL>>>();

    // Stage 5: output projection (fp32 output)
    dim3 g5(EE / BN, MTOK / BM, 1);               // (6, 256)
    out_mma_kernel<<<g5, 256, SMEM_TOTAL>>>(bo, out);
}